// round 1
// baseline (speedup 1.0000x reference)
#include <cuda_runtime.h>
#include <cstdint>

#define NMAX 50000
#define EMAX 1000000

// ---------------- scratch (static device globals; no allocation) ----------------
__device__ float g_deg[NMAX];                    // becomes 1/max(deg,1)
__device__ float g_xt[(size_t)NMAX * 320];       // [N][5*64] transformed feats (W0 | W_0..W_3)
__device__ float g_agg[(size_t)NMAX * 64];       // scatter accumulator
__device__ float g_h[(size_t)NMAX * 64];         // hidden state

// ---------------- packed fp32x2 helpers (sm_100+ full-rate FMA) ----------------
__device__ __forceinline__ void fma2(unsigned long long &a, unsigned long long x, unsigned long long w) {
    asm("fma.rn.f32x2 %0, %1, %2, %0;" : "+l"(a) : "l"(x), "l"(w));
}
__device__ __forceinline__ unsigned long long pack2(float v) {
    unsigned long long r;
    asm("mov.b64 %0, {%1, %1};" : "=l"(r) : "f"(v));
    return r;
}
__device__ __forceinline__ float2 unpack2(unsigned long long a) {
    float2 f;
    asm("mov.b64 {%0, %1}, %2;" : "=f"(f.x), "=f"(f.y) : "l"(a));
    return f;
}

// ---------------- degree ----------------
extern "C" __global__ void k_deg(const int* __restrict__ ei, float* __restrict__ deg, int E) {
    int e = blockIdx.x * blockDim.x + threadIdx.x;
    if (e < E) atomicAdd(&deg[ei[E + e]], 1.0f);
}
extern "C" __global__ void k_rdeg(float* __restrict__ deg, int N) {
    int i = blockIdx.x * blockDim.x + threadIdx.x;
    if (i < N) deg[i] = 1.0f / fmaxf(deg[i], 1.0f);
}

// ---------------- transform: out[N,320] = A[N,64] @ [W0 | Wr0..Wr3] ----------------
// block = 256 threads, 128 rows; weights loaded in 2 chunks of 160 cols.
extern "C" __global__ void __launch_bounds__(256, 3)
k_transform(const float* __restrict__ A, const float* __restrict__ W0,
            const float* __restrict__ Wr, float* __restrict__ out, int N) {
    extern __shared__ float sm[];
    float* xs = sm;              // 128*65 floats (padded, conflict-free)
    float* ws = sm + 128 * 65;   // 64*160 floats
    int t = threadIdx.x;
    int r0 = blockIdx.x * 128;

    for (int i = t; i < 128 * 64; i += 256) {
        int rr = i >> 6, k = i & 63;
        int g = r0 + rr;
        xs[rr * 65 + k] = (g < N) ? A[(size_t)g * 64 + k] : 0.f;
    }

    int row = t & 127, th = t >> 7;
    const float* xrow = &xs[row * 65];
    int gr = r0 + row;

    for (int ch = 0; ch < 2; ch++) {
        __syncthreads();
        for (int i = t; i < 64 * 160; i += 256) {
            int k = i / 160, cl = i - k * 160;
            int c = ch * 160 + cl;
            float v;
            if (c < 64) v = W0[k * 64 + c];
            else { int cc = c - 64; v = Wr[((cc >> 6) << 12) + k * 64 + (cc & 63)]; }
            ws[k * 160 + cl] = v;
        }
        __syncthreads();
        for (int jt = 0; jt < 10; jt++) {
            int jl = (jt * 2 + th) * 8;
            unsigned long long a0 = 0, a1 = 0, a2 = 0, a3 = 0;
            #pragma unroll
            for (int k = 0; k < 64; k++) {
                unsigned long long xv = pack2(xrow[k]);
                const float* wp = &ws[k * 160 + jl];
                ulonglong2 wA = *(const ulonglong2*)wp;
                ulonglong2 wB = *(const ulonglong2*)(wp + 4);
                fma2(a0, xv, wA.x); fma2(a1, xv, wA.y);
                fma2(a2, xv, wB.x); fma2(a3, xv, wB.y);
            }
            if (gr < N) {
                float2 f0 = unpack2(a0), f1 = unpack2(a1), f2 = unpack2(a2), f3 = unpack2(a3);
                float4* op = (float4*)&out[(size_t)gr * 320 + ch * 160 + jl];
                op[0] = make_float4(f0.x, f0.y, f1.x, f1.y);
                op[1] = make_float4(f2.x, f2.y, f3.x, f3.y);
            }
        }
    }
}

// ---------------- RGCN edge scatter: agg[dst] += w * xt[src, rel-block] ----------------
extern "C" __global__ void k_rgcn_scatter(const int* __restrict__ ei, const int* __restrict__ et,
                                          const float* __restrict__ ew, const float* __restrict__ xt,
                                          float* __restrict__ agg, int E) {
    int idx = blockIdx.x * blockDim.x + threadIdx.x;
    int e = idx >> 4;
    if (e >= E) return;
    int l = idx & 15;
    int src = ei[e], dst = ei[E + e];
    int r = et[e];
    float w = ew[e];
    float4 v = *(const float4*)&xt[(size_t)src * 320 + ((1 + r) << 6) + (l << 2)];
    float* p = &agg[((size_t)dst << 6) + (l << 2)];
    asm volatile("red.global.add.v4.f32 [%0], {%1,%2,%3,%4};"
                 :: "l"(p), "f"(v.x * w), "f"(v.y * w), "f"(v.z * w), "f"(v.w * w) : "memory");
}

// ---------------- Group edge scatter: agg[dst] += w * h[src] ----------------
extern "C" __global__ void k_group_scatter(const int* __restrict__ ei, const float* __restrict__ ew,
                                           const float* __restrict__ h, float* __restrict__ agg, int E) {
    int idx = blockIdx.x * blockDim.x + threadIdx.x;
    int e = idx >> 4;
    if (e >= E) return;
    int l = idx & 15;
    int src = ei[e], dst = ei[E + e];
    float w = ew[e];
    float4 v = *(const float4*)&h[((size_t)src << 6) + (l << 2)];
    float* p = &agg[((size_t)dst << 6) + (l << 2)];
    asm volatile("red.global.add.v4.f32 [%0], {%1,%2,%3,%4};"
                 :: "l"(p), "f"(v.x * w), "f"(v.y * w), "f"(v.z * w), "f"(v.w * w) : "memory");
}

// ---------------- RGCN combine: h = relu((xt[:,0:64] + agg) * rdeg) ----------------
extern "C" __global__ void k_combine_relu(const float* __restrict__ xt, const float* __restrict__ agg,
                                          const float* __restrict__ rdeg, float* __restrict__ h, int N) {
    int idx = blockIdx.x * blockDim.x + threadIdx.x;
    if (idx >= N * 16) return;
    int n = idx >> 4, l = idx & 15;
    float4 a = ((const float4*)(xt + (size_t)n * 320))[l];
    float4 g = ((const float4*)agg)[(size_t)n * 16 + l];
    float rd = rdeg[n];
    float4 o;
    o.x = fmaxf((a.x + g.x) * rd, 0.f);
    o.y = fmaxf((a.y + g.y) * rd, 0.f);
    o.z = fmaxf((a.z + g.z) * rd, 0.f);
    o.w = fmaxf((a.w + g.w) * rd, 0.f);
    ((float4*)h)[(size_t)n * 16 + l] = o;
}

// ---------------- Group combine: h += alpha * ((agg*rdeg) @ W + b) ----------------
extern "C" __global__ void __launch_bounds__(256, 4)
k_group_combine(const float* __restrict__ agg, const float* __restrict__ rdeg,
                const float* __restrict__ W, const float* __restrict__ b,
                const float* __restrict__ alpha_p, float* __restrict__ h, int N) {
    extern __shared__ float sm[];
    float* xs = sm;              // 128*65
    float* ws = sm + 128 * 65;   // 64*64
    int t = threadIdx.x;
    int r0 = blockIdx.x * 128;
    for (int i = t; i < 128 * 64; i += 256) {
        int rr = i >> 6, k = i & 63;
        int g = r0 + rr;
        xs[rr * 65 + k] = (g < N) ? agg[(size_t)g * 64 + k] * rdeg[g] : 0.f;
    }
    for (int i = t; i < 64 * 64; i += 256) ws[i] = W[i];
    __syncthreads();
    float alpha = *alpha_p;
    int row = t & 127, th = t >> 7;
    int gr = r0 + row;
    const float* xrow = &xs[row * 65];
    for (int jt = 0; jt < 4; jt++) {
        int jl = (jt * 2 + th) * 8;
        unsigned long long a0 = 0, a1 = 0, a2 = 0, a3 = 0;
        #pragma unroll
        for (int k = 0; k < 64; k++) {
            unsigned long long xv = pack2(xrow[k]);
            const float* wp = &ws[k * 64 + jl];
            ulonglong2 wA = *(const ulonglong2*)wp;
            ulonglong2 wB = *(const ulonglong2*)(wp + 4);
            fma2(a0, xv, wA.x); fma2(a1, xv, wA.y);
            fma2(a2, xv, wB.x); fma2(a3, xv, wB.y);
        }
        if (gr < N) {
            float2 f[4] = {unpack2(a0), unpack2(a1), unpack2(a2), unpack2(a3)};
            float* hp = &h[(size_t)gr * 64 + jl];
            const float* bp = &b[jl];
            #pragma unroll
            for (int q = 0; q < 4; q++) {
                hp[2 * q]     += alpha * (f[q].x + bp[2 * q]);
                hp[2 * q + 1] += alpha * (f[q].y + bp[2 * q + 1]);
            }
        }
    }
}

// ---------------- Output head: out = h @ outW[64,32] + outb ----------------
extern "C" __global__ void __launch_bounds__(256, 4)
k_head(const float* __restrict__ h, const float* __restrict__ W, const float* __restrict__ b,
       float* __restrict__ out, int N) {
    extern __shared__ float sm[];
    float* xs = sm;              // 128*65
    float* ws = sm + 128 * 65;   // 64*32
    int t = threadIdx.x;
    int r0 = blockIdx.x * 128;
    for (int i = t; i < 128 * 64; i += 256) {
        int rr = i >> 6, k = i & 63;
        int g = r0 + rr;
        xs[rr * 65 + k] = (g < N) ? h[(size_t)g * 64 + k] : 0.f;
    }
    for (int i = t; i < 64 * 32; i += 256) ws[i] = W[i];
    __syncthreads();
    int row = t & 127, th = t >> 7;
    int gr = r0 + row;
    const float* xrow = &xs[row * 65];
    for (int jt = 0; jt < 2; jt++) {
        int jl = (jt * 2 + th) * 8;
        unsigned long long a0 = 0, a1 = 0, a2 = 0, a3 = 0;
        #pragma unroll
        for (int k = 0; k < 64; k++) {
            unsigned long long xv = pack2(xrow[k]);
            const float* wp = &ws[k * 32 + jl];
            ulonglong2 wA = *(const ulonglong2*)wp;
            ulonglong2 wB = *(const ulonglong2*)(wp + 4);
            fma2(a0, xv, wA.x); fma2(a1, xv, wA.y);
            fma2(a2, xv, wB.x); fma2(a3, xv, wB.y);
        }
        if (gr < N) {
            float2 f0 = unpack2(a0), f1 = unpack2(a1), f2 = unpack2(a2), f3 = unpack2(a3);
            const float* bp = &b[jl];
            float* op = &out[(size_t)gr * 32 + jl];
            op[0] = f0.x + bp[0]; op[1] = f0.y + bp[1];
            op[2] = f1.x + bp[2]; op[3] = f1.y + bp[3];
            op[4] = f2.x + bp[4]; op[5] = f2.y + bp[5];
            op[6] = f3.x + bp[6]; op[7] = f3.y + bp[7];
        }
    }
}

// ---------------- launch ----------------
extern "C" void kernel_launch(void* const* d_in, const int* in_sizes, int n_in,
                              void* d_out, int out_size) {
    const float* x      = (const float*)d_in[0];
    const int*   ei     = (const int*)d_in[1];
    const int*   et     = (const int*)d_in[2];
    const float* ew     = (const float*)d_in[3];
    const float* W1     = (const float*)d_in[4];
    const float* W01    = (const float*)d_in[5];
    const float* alpha1 = (const float*)d_in[6];
    const float* projW1 = (const float*)d_in[7];
    const float* projb1 = (const float*)d_in[8];
    const float* W2     = (const float*)d_in[9];
    const float* W02    = (const float*)d_in[10];
    const float* alpha2 = (const float*)d_in[11];
    const float* projW2 = (const float*)d_in[12];
    const float* projb2 = (const float*)d_in[13];
    const float* outW   = (const float*)d_in[14];
    const float* outb   = (const float*)d_in[15];

    int N = in_sizes[0] / 64;
    int E = in_sizes[2];

    float *deg, *xt, *agg, *h;
    cudaGetSymbolAddress((void**)&deg, g_deg);
    cudaGetSymbolAddress((void**)&xt,  g_xt);
    cudaGetSymbolAddress((void**)&agg, g_agg);
    cudaGetSymbolAddress((void**)&h,   g_h);

    const int SMEM_T = (128 * 65 + 64 * 160) * 4;  // 74240
    const int SMEM_G = (128 * 65 + 64 * 64) * 4;   // 49664
    const int SMEM_H = (128 * 65 + 64 * 32) * 4;   // 41472
    cudaFuncSetAttribute(k_transform,     cudaFuncAttributeMaxDynamicSharedMemorySize, SMEM_T);
    cudaFuncSetAttribute(k_group_combine, cudaFuncAttributeMaxDynamicSharedMemorySize, SMEM_G);
    cudaFuncSetAttribute(k_head,          cudaFuncAttributeMaxDynamicSharedMemorySize, SMEM_H);

    int ebl  = (E + 255) / 256;
    int nbl  = (N + 255) / 256;
    int sbl  = (E * 16 + 255) / 256;
    int cbl  = (N * 16 + 255) / 256;
    int gbl  = (N + 127) / 128;
    size_t aggBytes = (size_t)N * 64 * sizeof(float);

    // degree
    cudaMemsetAsync(deg, 0, (size_t)N * sizeof(float));
    k_deg<<<ebl, 256>>>(ei, deg, E);
    k_rdeg<<<nbl, 256>>>(deg, N);

    // ---- layer 1: RGCN ----
    k_transform<<<gbl, 256, SMEM_T>>>(x, W01, W1, xt, N);
    cudaMemsetAsync(agg, 0, aggBytes);
    k_rgcn_scatter<<<sbl, 256>>>(ei, et, ew, xt, agg, E);
    k_combine_relu<<<cbl, 256>>>(xt, agg, deg, h, N);
    // ---- layer 1: Group ----
    cudaMemsetAsync(agg, 0, aggBytes);
    k_group_scatter<<<sbl, 256>>>(ei, ew, h, agg, E);
    k_group_combine<<<gbl, 256, SMEM_G>>>(agg, deg, projW1, projb1, alpha1, h, N);

    // ---- layer 2: RGCN ----
    k_transform<<<gbl, 256, SMEM_T>>>(h, W02, W2, xt, N);
    cudaMemsetAsync(agg, 0, aggBytes);
    k_rgcn_scatter<<<sbl, 256>>>(ei, et, ew, xt, agg, E);
    k_combine_relu<<<cbl, 256>>>(xt, agg, deg, h, N);
    // ---- layer 2: Group ----
    cudaMemsetAsync(agg, 0, aggBytes);
    k_group_scatter<<<sbl, 256>>>(ei, ew, h, agg, E);
    k_group_combine<<<gbl, 256, SMEM_G>>>(agg, deg, projW2, projb2, alpha2, h, N);

    // ---- head ----
    k_head<<<gbl, 256, SMEM_H>>>(h, outW, outb, (float*)d_out, N);
}

// round 2
// speedup vs baseline: 1.5556x; 1.5556x over previous
#include <cuda_runtime.h>
#include <cstdint>

#define NMAX 50000
#define EMAX 1000000

// ---------------- scratch (static device globals; no allocation) ----------------
__device__ float g_rdeg[NMAX];                   // 1/max(deg,1)
__device__ int   g_cnt[NMAX];                    // in-degree counts
__device__ int   g_off[NMAX + 1];                // CSR offsets (exclusive scan)
__device__ int   g_cursor[NMAX];                 // fill cursors
__device__ int   g_bsum[64];                     // scan block sums
__device__ int2  g_erec[EMAX];                   // CSR edge records {src|rel<<17, w_bits}
__device__ float g_xt[(size_t)NMAX * 320];       // transformed feats [W0 | Wr0..Wr3]
__device__ float g_agg[(size_t)NMAX * 64];       // group aggregation buffer
__device__ float g_h[(size_t)NMAX * 64];         // hidden state

// ---------------- packed fp32x2 helpers ----------------
__device__ __forceinline__ void fma2(unsigned long long &a, unsigned long long x, unsigned long long w) {
    asm("fma.rn.f32x2 %0, %1, %2, %0;" : "+l"(a) : "l"(x), "l"(w));
}
__device__ __forceinline__ unsigned long long pack2(float v) {
    unsigned long long r;
    asm("mov.b64 %0, {%1, %1};" : "=l"(r) : "f"(v));
    return r;
}
__device__ __forceinline__ float2 unpack2(unsigned long long a) {
    float2 f;
    asm("mov.b64 {%0, %1}, %2;" : "=f"(f.x), "=f"(f.y) : "l"(a));
    return f;
}

// ---------------- degree / CSR build ----------------
extern "C" __global__ void k_deg(const int* __restrict__ ei, int* __restrict__ cnt, int E) {
    int e = blockIdx.x * blockDim.x + threadIdx.x;
    if (e < E) atomicAdd(&cnt[ei[E + e]], 1);
}
extern "C" __global__ void k_rdeg(const int* __restrict__ cnt, float* __restrict__ rdeg, int N) {
    int i = blockIdx.x * blockDim.x + threadIdx.x;
    if (i < N) rdeg[i] = 1.0f / (float)max(cnt[i], 1);
}
// block-level exclusive scan (1024 threads/block)
extern "C" __global__ void k_scan1(const int* __restrict__ cnt, int* __restrict__ off,
                                   int* __restrict__ bsum, int N) {
    __shared__ int wsum[32];
    int t = threadIdx.x, g = blockIdx.x * 1024 + t;
    int v = (g < N) ? cnt[g] : 0;
    int lane = t & 31, wid = t >> 5;
    int x = v;
    #pragma unroll
    for (int d = 1; d < 32; d <<= 1) {
        int y = __shfl_up_sync(0xFFFFFFFF, x, d);
        if (lane >= d) x += y;
    }
    if (lane == 31) wsum[wid] = x;
    __syncthreads();
    if (wid == 0) {
        int s = wsum[lane];
        #pragma unroll
        for (int d = 1; d < 32; d <<= 1) {
            int y = __shfl_up_sync(0xFFFFFFFF, s, d);
            if (lane >= d) s += y;
        }
        wsum[lane] = s;
    }
    __syncthreads();
    int incl = x + (wid > 0 ? wsum[wid - 1] : 0);
    if (g < N) off[g] = incl - v;
    if (t == 1023) bsum[blockIdx.x] = incl;
}
extern "C" __global__ void k_scan2(int* __restrict__ bsum, int B) {
    __shared__ int s[64];
    int t = threadIdx.x;
    s[t] = (t < B) ? bsum[t] : 0;
    __syncthreads();
    if (t == 0) {
        int run = 0;
        for (int i = 0; i < B; i++) { int v = s[i]; s[i] = run; run += v; }
    }
    __syncthreads();
    if (t < B) bsum[t] = s[t];
}
extern "C" __global__ void k_scan3(int* __restrict__ off, int* __restrict__ cursor,
                                   const int* __restrict__ bsum, int N, int E) {
    int g = blockIdx.x * blockDim.x + threadIdx.x;
    if (g < N) {
        int o = off[g] + bsum[g >> 10];
        off[g] = o;
        cursor[g] = o;
    }
    if (g == 0) off[N] = E;
}
extern "C" __global__ void k_fill(const int* __restrict__ ei, const int* __restrict__ et,
                                  const float* __restrict__ ew, int* __restrict__ cursor,
                                  int2* __restrict__ erec, int E) {
    int e = blockIdx.x * blockDim.x + threadIdx.x;
    if (e >= E) return;
    int dst = ei[E + e];
    int pos = atomicAdd(&cursor[dst], 1);
    erec[pos] = make_int2(ei[e] | (et[e] << 17), __float_as_int(ew[e]));
}

// ---------------- transform: out[N,320] = A[N,64] @ [W0 | Wr0..Wr3] ----------------
// Register-tiled: block=256, tile 128 rows x 320 cols (5 passes of 64 cols).
// Thread computes 4 rows x 8 cols. x transposed in smem so rows load as float4.
#define XS_P 132
extern "C" __global__ void __launch_bounds__(256)
k_transform(const float* __restrict__ A, const float* __restrict__ W0,
            const float* __restrict__ Wr, float* __restrict__ out, int N) {
    extern __shared__ float sm[];
    float* xs = sm;              // [64][XS_P]  (k-major, transposed)
    float* ws = sm + 64 * XS_P;  // [64][64]
    int t = threadIdx.x;
    int r0 = blockIdx.x * 128;

    for (int i = t; i < 128 * 64; i += 256) {
        int row = i >> 6, k = i & 63;
        int g = r0 + row;
        xs[k * XS_P + row] = (g < N) ? A[(size_t)g * 64 + k] : 0.f;
    }

    int tx = t & 7, ty = t >> 3;          // tx: col-group (8 cols), ty: row-group (4 rows)
    const float* xp = &xs[4 * ty];

    for (int pass = 0; pass < 5; pass++) {
        __syncthreads();
        for (int i = t; i < 64 * 64; i += 256)
            ws[i] = (pass == 0) ? W0[i] : Wr[(pass - 1) * 4096 + i];
        __syncthreads();

        unsigned long long acc[4][4];
        #pragma unroll
        for (int r = 0; r < 4; r++)
            #pragma unroll
            for (int j = 0; j < 4; j++) acc[r][j] = 0ULL;

        #pragma unroll 4
        for (int k = 0; k < 64; k++) {
            float4 xv = *(const float4*)&xp[k * XS_P];
            ulonglong2 wA = *(const ulonglong2*)&ws[k * 64 + 8 * tx];
            ulonglong2 wB = *(const ulonglong2*)&ws[k * 64 + 8 * tx + 4];
            unsigned long long x0 = pack2(xv.x), x1 = pack2(xv.y),
                               x2 = pack2(xv.z), x3 = pack2(xv.w);
            fma2(acc[0][0], x0, wA.x); fma2(acc[0][1], x0, wA.y);
            fma2(acc[0][2], x0, wB.x); fma2(acc[0][3], x0, wB.y);
            fma2(acc[1][0], x1, wA.x); fma2(acc[1][1], x1, wA.y);
            fma2(acc[1][2], x1, wB.x); fma2(acc[1][3], x1, wB.y);
            fma2(acc[2][0], x2, wA.x); fma2(acc[2][1], x2, wA.y);
            fma2(acc[2][2], x2, wB.x); fma2(acc[2][3], x2, wB.y);
            fma2(acc[3][0], x3, wA.x); fma2(acc[3][1], x3, wA.y);
            fma2(acc[3][2], x3, wB.x); fma2(acc[3][3], x3, wB.y);
        }
        #pragma unroll
        for (int r = 0; r < 4; r++) {
            int gr = r0 + 4 * ty + r;
            if (gr < N) {
                unsigned long long* op =
                    (unsigned long long*)&out[(size_t)gr * 320 + pass * 64 + 8 * tx];
                *(ulonglong2*)op       = make_ulonglong2(acc[r][0], acc[r][1]);
                *(ulonglong2*)(op + 2) = make_ulonglong2(acc[r][2], acc[r][3]);
            }
        }
    }
}

// ---------------- RGCN gather + fused combine/relu ----------------
// 16 lanes per node: agg = sum_e w_e * xt[src_e, rel-block]; h = relu((xt0+agg)*rdeg)
extern "C" __global__ void k_rgcn_gather(const int* __restrict__ off, const int2* __restrict__ erec,
                                         const float* __restrict__ xt, const float* __restrict__ rdeg,
                                         float* __restrict__ h, int N) {
    int idx = blockIdx.x * blockDim.x + threadIdx.x;
    int node = idx >> 4;
    if (node >= N) return;
    int lane = idx & 15;
    int beg = off[node], end = off[node + 1];
    float4 a0 = {0, 0, 0, 0}, a1 = {0, 0, 0, 0};
    int i = beg;
    for (; i + 2 <= end; i += 2) {
        int2 r0 = __ldg(&erec[i]), r1 = __ldg(&erec[i + 1]);
        int s0 = r0.x & 0x1FFFF, s1 = r1.x & 0x1FFFF;
        int q0 = (r0.x >> 17) + 1, q1 = (r1.x >> 17) + 1;
        float w0 = __int_as_float(r0.y), w1 = __int_as_float(r1.y);
        float4 v0 = __ldg((const float4*)&xt[(size_t)s0 * 320 + (q0 << 6) + (lane << 2)]);
        float4 v1 = __ldg((const float4*)&xt[(size_t)s1 * 320 + (q1 << 6) + (lane << 2)]);
        a0.x += w0 * v0.x; a0.y += w0 * v0.y; a0.z += w0 * v0.z; a0.w += w0 * v0.w;
        a1.x += w1 * v1.x; a1.y += w1 * v1.y; a1.z += w1 * v1.z; a1.w += w1 * v1.w;
    }
    if (i < end) {
        int2 r0 = __ldg(&erec[i]);
        int s0 = r0.x & 0x1FFFF;
        int q0 = (r0.x >> 17) + 1;
        float w0 = __int_as_float(r0.y);
        float4 v0 = __ldg((const float4*)&xt[(size_t)s0 * 320 + (q0 << 6) + (lane << 2)]);
        a0.x += w0 * v0.x; a0.y += w0 * v0.y; a0.z += w0 * v0.z; a0.w += w0 * v0.w;
    }
    float4 s = *(const float4*)&xt[(size_t)node * 320 + (lane << 2)];
    float rd = rdeg[node];
    float4 o;
    o.x = fmaxf((s.x + a0.x + a1.x) * rd, 0.f);
    o.y = fmaxf((s.y + a0.y + a1.y) * rd, 0.f);
    o.z = fmaxf((s.z + a0.z + a1.z) * rd, 0.f);
    o.w = fmaxf((s.w + a0.w + a1.w) * rd, 0.f);
    *(float4*)&h[((size_t)node << 6) + (lane << 2)] = o;
}

// ---------------- Group gather: agg[n] = sum_e w_e * h[src_e] ----------------
extern "C" __global__ void k_group_gather(const int* __restrict__ off, const int2* __restrict__ erec,
                                          const float* __restrict__ h, float* __restrict__ agg, int N) {
    int idx = blockIdx.x * blockDim.x + threadIdx.x;
    int node = idx >> 4;
    if (node >= N) return;
    int lane = idx & 15;
    int beg = off[node], end = off[node + 1];
    float4 a0 = {0, 0, 0, 0}, a1 = {0, 0, 0, 0};
    int i = beg;
    for (; i + 2 <= end; i += 2) {
        int2 r0 = __ldg(&erec[i]), r1 = __ldg(&erec[i + 1]);
        int s0 = r0.x & 0x1FFFF, s1 = r1.x & 0x1FFFF;
        float w0 = __int_as_float(r0.y), w1 = __int_as_float(r1.y);
        float4 v0 = __ldg((const float4*)&h[((size_t)s0 << 6) + (lane << 2)]);
        float4 v1 = __ldg((const float4*)&h[((size_t)s1 << 6) + (lane << 2)]);
        a0.x += w0 * v0.x; a0.y += w0 * v0.y; a0.z += w0 * v0.z; a0.w += w0 * v0.w;
        a1.x += w1 * v1.x; a1.y += w1 * v1.y; a1.z += w1 * v1.z; a1.w += w1 * v1.w;
    }
    if (i < end) {
        int2 r0 = __ldg(&erec[i]);
        int s0 = r0.x & 0x1FFFF;
        float w0 = __int_as_float(r0.y);
        float4 v0 = __ldg((const float4*)&h[((size_t)s0 << 6) + (lane << 2)]);
        a0.x += w0 * v0.x; a0.y += w0 * v0.y; a0.z += w0 * v0.z; a0.w += w0 * v0.w;
    }
    float4 o;
    o.x = a0.x + a1.x; o.y = a0.y + a1.y; o.z = a0.z + a1.z; o.w = a0.w + a1.w;
    *(float4*)&agg[((size_t)node << 6) + (lane << 2)] = o;
}

// ---------------- Group combine: h += alpha * ((agg*rdeg) @ W + b), register-tiled ----------------
extern "C" __global__ void __launch_bounds__(256)
k_group_combine(const float* __restrict__ agg, const float* __restrict__ rdeg,
                const float* __restrict__ W, const float* __restrict__ b,
                const float* __restrict__ alpha_p, float* __restrict__ h, int N) {
    extern __shared__ float sm[];
    float* xs = sm;              // [64][XS_P]
    float* ws = sm + 64 * XS_P;  // [64][64]
    int t = threadIdx.x;
    int r0 = blockIdx.x * 128;

    for (int i = t; i < 128 * 64; i += 256) {
        int row = i >> 6, k = i & 63;
        int g = r0 + row;
        xs[k * XS_P + row] = (g < N) ? agg[(size_t)g * 64 + k] * rdeg[g] : 0.f;
    }
    for (int i = t; i < 64 * 64; i += 256) ws[i] = W[i];
    __syncthreads();

    float alpha = *alpha_p;
    int tx = t & 7, ty = t >> 3;
    const float* xp = &xs[4 * ty];

    unsigned long long acc[4][4];
    #pragma unroll
    for (int r = 0; r < 4; r++)
        #pragma unroll
        for (int j = 0; j < 4; j++) acc[r][j] = 0ULL;

    #pragma unroll 4
    for (int k = 0; k < 64; k++) {
        float4 xv = *(const float4*)&xp[k * XS_P];
        ulonglong2 wA = *(const ulonglong2*)&ws[k * 64 + 8 * tx];
        ulonglong2 wB = *(const ulonglong2*)&ws[k * 64 + 8 * tx + 4];
        unsigned long long x0 = pack2(xv.x), x1 = pack2(xv.y),
                           x2 = pack2(xv.z), x3 = pack2(xv.w);
        fma2(acc[0][0], x0, wA.x); fma2(acc[0][1], x0, wA.y);
        fma2(acc[0][2], x0, wB.x); fma2(acc[0][3], x0, wB.y);
        fma2(acc[1][0], x1, wA.x); fma2(acc[1][1], x1, wA.y);
        fma2(acc[1][2], x1, wB.x); fma2(acc[1][3], x1, wB.y);
        fma2(acc[2][0], x2, wA.x); fma2(acc[2][1], x2, wA.y);
        fma2(acc[2][2], x2, wB.x); fma2(acc[2][3], x2, wB.y);
        fma2(acc[3][0], x3, wA.x); fma2(acc[3][1], x3, wA.y);
        fma2(acc[3][2], x3, wB.x); fma2(acc[3][3], x3, wB.y);
    }
    float4 b0 = *(const float4*)&b[8 * tx];
    float4 b1 = *(const float4*)&b[8 * tx + 4];
    #pragma unroll
    for (int r = 0; r < 4; r++) {
        int gr = r0 + 4 * ty + r;
        if (gr < N) {
            float* hp = &h[((size_t)gr << 6) + 8 * tx];
            float4 h0 = *(float4*)hp;
            float4 h1 = *(float4*)(hp + 4);
            float2 f0 = unpack2(acc[r][0]), f1 = unpack2(acc[r][1]);
            float2 f2 = unpack2(acc[r][2]), f3 = unpack2(acc[r][3]);
            h0.x += alpha * (f0.x + b0.x); h0.y += alpha * (f0.y + b0.y);
            h0.z += alpha * (f1.x + b0.z); h0.w += alpha * (f1.y + b0.w);
            h1.x += alpha * (f2.x + b1.x); h1.y += alpha * (f2.y + b1.y);
            h1.z += alpha * (f3.x + b1.z); h1.w += alpha * (f3.y + b1.w);
            *(float4*)hp = h0;
            *(float4*)(hp + 4) = h1;
        }
    }
}

// ---------------- Output head: out = h @ outW[64,32] + outb ----------------
extern "C" __global__ void __launch_bounds__(256, 4)
k_head(const float* __restrict__ h, const float* __restrict__ W, const float* __restrict__ b,
       float* __restrict__ out, int N) {
    extern __shared__ float sm[];
    float* xs = sm;              // 128*65
    float* ws = sm + 128 * 65;   // 64*32
    int t = threadIdx.x;
    int r0 = blockIdx.x * 128;
    for (int i = t; i < 128 * 64; i += 256) {
        int rr = i >> 6, k = i & 63;
        int g = r0 + rr;
        xs[rr * 65 + k] = (g < N) ? h[(size_t)g * 64 + k] : 0.f;
    }
    for (int i = t; i < 64 * 32; i += 256) ws[i] = W[i];
    __syncthreads();
    int row = t & 127, th = t >> 7;
    int gr = r0 + row;
    const float* xrow = &xs[row * 65];
    for (int jt = 0; jt < 2; jt++) {
        int jl = (jt * 2 + th) * 8;
        unsigned long long a0 = 0, a1 = 0, a2 = 0, a3 = 0;
        #pragma unroll
        for (int k = 0; k < 64; k++) {
            unsigned long long xv = pack2(xrow[k]);
            const float* wp = &ws[k * 32 + jl];
            ulonglong2 wA = *(const ulonglong2*)wp;
            ulonglong2 wB = *(const ulonglong2*)(wp + 4);
            fma2(a0, xv, wA.x); fma2(a1, xv, wA.y);
            fma2(a2, xv, wB.x); fma2(a3, xv, wB.y);
        }
        if (gr < N) {
            float2 f0 = unpack2(a0), f1 = unpack2(a1), f2 = unpack2(a2), f3 = unpack2(a3);
            const float* bp = &b[jl];
            float* op = &out[(size_t)gr * 32 + jl];
            op[0] = f0.x + bp[0]; op[1] = f0.y + bp[1];
            op[2] = f1.x + bp[2]; op[3] = f1.y + bp[3];
            op[4] = f2.x + bp[4]; op[5] = f2.y + bp[5];
            op[6] = f3.x + bp[6]; op[7] = f3.y + bp[7];
        }
    }
}

// ---------------- launch ----------------
extern "C" void kernel_launch(void* const* d_in, const int* in_sizes, int n_in,
                              void* d_out, int out_size) {
    const float* x      = (const float*)d_in[0];
    const int*   ei     = (const int*)d_in[1];
    const int*   et     = (const int*)d_in[2];
    const float* ew     = (const float*)d_in[3];
    const float* W1     = (const float*)d_in[4];
    const float* W01    = (const float*)d_in[5];
    const float* alpha1 = (const float*)d_in[6];
    const float* projW1 = (const float*)d_in[7];
    const float* projb1 = (const float*)d_in[8];
    const float* W2     = (const float*)d_in[9];
    const float* W02    = (const float*)d_in[10];
    const float* alpha2 = (const float*)d_in[11];
    const float* projW2 = (const float*)d_in[12];
    const float* projb2 = (const float*)d_in[13];
    const float* outW   = (const float*)d_in[14];
    const float* outb   = (const float*)d_in[15];

    int N = in_sizes[0] / 64;
    int E = in_sizes[2];

    float *rdeg, *xt, *agg, *h;
    int *cnt, *off, *cursor, *bsum;
    int2 *erec;
    cudaGetSymbolAddress((void**)&rdeg,   g_rdeg);
    cudaGetSymbolAddress((void**)&cnt,    g_cnt);
    cudaGetSymbolAddress((void**)&off,    g_off);
    cudaGetSymbolAddress((void**)&cursor, g_cursor);
    cudaGetSymbolAddress((void**)&bsum,   g_bsum);
    cudaGetSymbolAddress((void**)&erec,   g_erec);
    cudaGetSymbolAddress((void**)&xt,     g_xt);
    cudaGetSymbolAddress((void**)&agg,    g_agg);
    cudaGetSymbolAddress((void**)&h,      g_h);

    const int SMEM_T = (64 * XS_P + 64 * 64) * 4;  // 50176
    const int SMEM_H = (128 * 65 + 64 * 32) * 4;   // 41472
    cudaFuncSetAttribute(k_transform,     cudaFuncAttributeMaxDynamicSharedMemorySize, SMEM_T);
    cudaFuncSetAttribute(k_group_combine, cudaFuncAttributeMaxDynamicSharedMemorySize, SMEM_T);
    cudaFuncSetAttribute(k_head,          cudaFuncAttributeMaxDynamicSharedMemorySize, SMEM_H);

    int ebl = (E + 255) / 256;
    int nbl = (N + 255) / 256;
    int gthr = (N * 16 + 255) / 256;   // gather kernels
    int gbl  = (N + 127) / 128;        // GEMM tiles
    int B1   = (N + 1023) / 1024;      // scan blocks

    // ---- CSR build ----
    cudaMemsetAsync(cnt, 0, (size_t)N * sizeof(int));
    k_deg<<<ebl, 256>>>(ei, cnt, E);
    k_rdeg<<<nbl, 256>>>(cnt, rdeg, N);
    k_scan1<<<B1, 1024>>>(cnt, off, bsum, N);
    k_scan2<<<1, 64>>>(bsum, B1);
    k_scan3<<<nbl, 256>>>(off, cursor, bsum, N, E);
    k_fill<<<ebl, 256>>>(ei, et, ew, cursor, erec, E);

    // ---- layer 1 ----
    k_transform<<<gbl, 256, SMEM_T>>>(x, W01, W1, xt, N);
    k_rgcn_gather<<<gthr, 256>>>(off, erec, xt, rdeg, h, N);
    k_group_gather<<<gthr, 256>>>(off, erec, h, agg, N);
    k_group_combine<<<gbl, 256, SMEM_T>>>(agg, rdeg, projW1, projb1, alpha1, h, N);

    // ---- layer 2 ----
    k_transform<<<gbl, 256, SMEM_T>>>(h, W02, W2, xt, N);
    k_rgcn_gather<<<gthr, 256>>>(off, erec, xt, rdeg, h, N);
    k_group_gather<<<gthr, 256>>>(off, erec, h, agg, N);
    k_group_combine<<<gbl, 256, SMEM_T>>>(agg, rdeg, projW2, projb2, alpha2, h, N);

    // ---- head ----
    k_head<<<gbl, 256, SMEM_H>>>(h, outW, outb, (float*)d_out, N);
}

// round 3
// speedup vs baseline: 1.6168x; 1.0394x over previous
#include <cuda_runtime.h>
#include <cstdint>

#define NMAX 50000
#define EMAX 1000000

// ---------------- scratch (static device globals; no allocation) ----------------
__device__ float g_rdeg[NMAX];
__device__ int   g_cnt[NMAX];
__device__ int   g_off[NMAX + 1];
__device__ int   g_cursor[NMAX];
__device__ int   g_bsum[64];
__device__ int2  g_erec[EMAX];                   // {src | rel<<17, w_bits}
__device__ float g_xt[(size_t)NMAX * 320];
__device__ float g_agg[(size_t)NMAX * 64];
__device__ float g_h[(size_t)NMAX * 64];

// ---------------- packed fp32x2 helpers ----------------
__device__ __forceinline__ void fma2(unsigned long long &a, unsigned long long x, unsigned long long w) {
    asm("fma.rn.f32x2 %0, %1, %2, %0;" : "+l"(a) : "l"(x), "l"(w));
}
__device__ __forceinline__ unsigned long long pack2(float v) {
    unsigned long long r;
    asm("mov.b64 %0, {%1, %1};" : "=l"(r) : "f"(v));
    return r;
}
__device__ __forceinline__ float2 unpack2(unsigned long long a) {
    float2 f;
    asm("mov.b64 {%0, %1}, %2;" : "=f"(f.x), "=f"(f.y) : "l"(a));
    return f;
}

// ---------------- degree / CSR build ----------------
extern "C" __global__ void k_deg(const int* __restrict__ ei, int* __restrict__ cnt, int E) {
    int e = blockIdx.x * blockDim.x + threadIdx.x;
    if (e < E) atomicAdd(&cnt[ei[E + e]], 1);
}
// exclusive scan over 1024-blocks; also emits rdeg = 1/max(cnt,1)
extern "C" __global__ void k_scan1(const int* __restrict__ cnt, int* __restrict__ off,
                                   float* __restrict__ rdeg, int* __restrict__ bsum, int N) {
    __shared__ int wsum[32];
    int t = threadIdx.x, g = blockIdx.x * 1024 + t;
    int v = (g < N) ? cnt[g] : 0;
    int lane = t & 31, wid = t >> 5;
    int x = v;
    #pragma unroll
    for (int d = 1; d < 32; d <<= 1) {
        int y = __shfl_up_sync(0xFFFFFFFF, x, d);
        if (lane >= d) x += y;
    }
    if (lane == 31) wsum[wid] = x;
    __syncthreads();
    if (wid == 0) {
        int s = wsum[lane];
        #pragma unroll
        for (int d = 1; d < 32; d <<= 1) {
            int y = __shfl_up_sync(0xFFFFFFFF, s, d);
            if (lane >= d) s += y;
        }
        wsum[lane] = s;
    }
    __syncthreads();
    int incl = x + (wid > 0 ? wsum[wid - 1] : 0);
    if (g < N) {
        off[g] = incl - v;
        rdeg[g] = 1.0f / (float)max(v, 1);
    }
    if (t == 1023) bsum[blockIdx.x] = incl;
}
extern "C" __global__ void k_scan2(int* __restrict__ bsum, int B) {
    __shared__ int s[64];
    int t = threadIdx.x;
    s[t] = (t < B) ? bsum[t] : 0;
    __syncthreads();
    if (t == 0) {
        int run = 0;
        for (int i = 0; i < B; i++) { int v = s[i]; s[i] = run; run += v; }
    }
    __syncthreads();
    if (t < B) bsum[t] = s[t];
}
extern "C" __global__ void k_scan3(int* __restrict__ off, int* __restrict__ cursor,
                                   const int* __restrict__ bsum, int N, int E) {
    int g = blockIdx.x * blockDim.x + threadIdx.x;
    if (g < N) {
        int o = off[g] + bsum[g >> 10];
        off[g] = o;
        cursor[g] = o;
    }
    if (g == 0) off[N] = E;
}
extern "C" __global__ void k_fill(const int* __restrict__ ei, const int* __restrict__ et,
                                  const float* __restrict__ ew, int* __restrict__ cursor,
                                  int2* __restrict__ erec, int E) {
    int e = blockIdx.x * blockDim.x + threadIdx.x;
    if (e >= E) return;
    int dst = ei[E + e];
    int pos = atomicAdd(&cursor[dst], 1);
    erec[pos] = make_int2(ei[e] | (et[e] << 17), __float_as_int(ew[e]));
}

// ---------------- transform: out[N,320] = A[N,64] @ [W0 | Wr0..Wr3] ----------------
#define XS_P 132
extern "C" __global__ void __launch_bounds__(256)
k_transform(const float* __restrict__ A, const float* __restrict__ W0,
            const float* __restrict__ Wr, float* __restrict__ out, int N) {
    extern __shared__ float sm[];
    float* xs = sm;              // [64][XS_P] k-major
    float* ws = sm + 64 * XS_P;  // [64][64]
    int t = threadIdx.x;
    int r0 = blockIdx.x * 128;

    for (int i = t; i < 128 * 64; i += 256) {
        int row = i >> 6, k = i & 63;
        int g = r0 + row;
        xs[k * XS_P + row] = (g < N) ? A[(size_t)g * 64 + k] : 0.f;
    }

    int tx = t & 7, ty = t >> 3;
    const float* xp = &xs[4 * ty];

    for (int pass = 0; pass < 5; pass++) {
        __syncthreads();
        for (int i = t; i < 64 * 64; i += 256)
            ws[i] = (pass == 0) ? W0[i] : Wr[(pass - 1) * 4096 + i];
        __syncthreads();

        unsigned long long acc[4][4];
        #pragma unroll
        for (int r = 0; r < 4; r++)
            #pragma unroll
            for (int j = 0; j < 4; j++) acc[r][j] = 0ULL;

        #pragma unroll 4
        for (int k = 0; k < 64; k++) {
            float4 xv = *(const float4*)&xp[k * XS_P];
            ulonglong2 wA = *(const ulonglong2*)&ws[k * 64 + 8 * tx];
            ulonglong2 wB = *(const ulonglong2*)&ws[k * 64 + 8 * tx + 4];
            unsigned long long x0 = pack2(xv.x), x1 = pack2(xv.y),
                               x2 = pack2(xv.z), x3 = pack2(xv.w);
            fma2(acc[0][0], x0, wA.x); fma2(acc[0][1], x0, wA.y);
            fma2(acc[0][2], x0, wB.x); fma2(acc[0][3], x0, wB.y);
            fma2(acc[1][0], x1, wA.x); fma2(acc[1][1], x1, wA.y);
            fma2(acc[1][2], x1, wB.x); fma2(acc[1][3], x1, wB.y);
            fma2(acc[2][0], x2, wA.x); fma2(acc[2][1], x2, wA.y);
            fma2(acc[2][2], x2, wB.x); fma2(acc[2][3], x2, wB.y);
            fma2(acc[3][0], x3, wA.x); fma2(acc[3][1], x3, wA.y);
            fma2(acc[3][2], x3, wB.x); fma2(acc[3][3], x3, wB.y);
        }
        #pragma unroll
        for (int r = 0; r < 4; r++) {
            int gr = r0 + 4 * ty + r;
            if (gr < N) {
                unsigned long long* op =
                    (unsigned long long*)&out[(size_t)gr * 320 + pass * 64 + 8 * tx];
                *(ulonglong2*)op       = make_ulonglong2(acc[r][0], acc[r][1]);
                *(ulonglong2*)(op + 2) = make_ulonglong2(acc[r][2], acc[r][3]);
            }
        }
    }
}

// ---------------- RGCN gather (4-way unrolled) + fused combine/relu ----------------
extern "C" __global__ void k_rgcn_gather(const int* __restrict__ off, const int2* __restrict__ erec,
                                         const float* __restrict__ xt, const float* __restrict__ rdeg,
                                         float* __restrict__ h, int N) {
    int idx = blockIdx.x * blockDim.x + threadIdx.x;
    int node = idx >> 4;
    if (node >= N) return;
    int lane = idx & 15;
    int beg = off[node], end = off[node + 1];
    const float4* xt4 = (const float4*)xt;   // row stride 80 float4s
    float4 a0 = {0,0,0,0}, a1 = {0,0,0,0}, a2 = {0,0,0,0}, a3 = {0,0,0,0};
    int i = beg;
    for (; i + 4 <= end; i += 4) {
        int2 r0 = __ldg(&erec[i]),     r1 = __ldg(&erec[i + 1]);
        int2 r2 = __ldg(&erec[i + 2]), r3 = __ldg(&erec[i + 3]);
        float4 v0 = __ldg(&xt4[(size_t)(r0.x & 0x1FFFF) * 80 + (((r0.x >> 17) + 1) << 4) + lane]);
        float4 v1 = __ldg(&xt4[(size_t)(r1.x & 0x1FFFF) * 80 + (((r1.x >> 17) + 1) << 4) + lane]);
        float4 v2 = __ldg(&xt4[(size_t)(r2.x & 0x1FFFF) * 80 + (((r2.x >> 17) + 1) << 4) + lane]);
        float4 v3 = __ldg(&xt4[(size_t)(r3.x & 0x1FFFF) * 80 + (((r3.x >> 17) + 1) << 4) + lane]);
        float w0 = __int_as_float(r0.y), w1 = __int_as_float(r1.y);
        float w2 = __int_as_float(r2.y), w3 = __int_as_float(r3.y);
        a0.x += w0*v0.x; a0.y += w0*v0.y; a0.z += w0*v0.z; a0.w += w0*v0.w;
        a1.x += w1*v1.x; a1.y += w1*v1.y; a1.z += w1*v1.z; a1.w += w1*v1.w;
        a2.x += w2*v2.x; a2.y += w2*v2.y; a2.z += w2*v2.z; a2.w += w2*v2.w;
        a3.x += w3*v3.x; a3.y += w3*v3.y; a3.z += w3*v3.z; a3.w += w3*v3.w;
    }
    for (; i < end; i++) {
        int2 r0 = __ldg(&erec[i]);
        float w0 = __int_as_float(r0.y);
        float4 v0 = __ldg(&xt4[(size_t)(r0.x & 0x1FFFF) * 80 + (((r0.x >> 17) + 1) << 4) + lane]);
        a0.x += w0*v0.x; a0.y += w0*v0.y; a0.z += w0*v0.z; a0.w += w0*v0.w;
    }
    float4 s = __ldg(&xt4[(size_t)node * 80 + lane]);
    float rd = rdeg[node];
    float4 o;
    o.x = fmaxf((s.x + (a0.x + a1.x) + (a2.x + a3.x)) * rd, 0.f);
    o.y = fmaxf((s.y + (a0.y + a1.y) + (a2.y + a3.y)) * rd, 0.f);
    o.z = fmaxf((s.z + (a0.z + a1.z) + (a2.z + a3.z)) * rd, 0.f);
    o.w = fmaxf((s.w + (a0.w + a1.w) + (a2.w + a3.w)) * rd, 0.f);
    *(float4*)&h[((size_t)node << 6) + (lane << 2)] = o;
}

// ---------------- Group gather (4-way unrolled): agg[n] = sum_e w_e * h[src_e] ----------------
extern "C" __global__ void k_group_gather(const int* __restrict__ off, const int2* __restrict__ erec,
                                          const float* __restrict__ h, float* __restrict__ agg, int N) {
    int idx = blockIdx.x * blockDim.x + threadIdx.x;
    int node = idx >> 4;
    if (node >= N) return;
    int lane = idx & 15;
    int beg = off[node], end = off[node + 1];
    const float4* h4 = (const float4*)h;   // row stride 16 float4s
    float4 a0 = {0,0,0,0}, a1 = {0,0,0,0}, a2 = {0,0,0,0}, a3 = {0,0,0,0};
    int i = beg;
    for (; i + 4 <= end; i += 4) {
        int2 r0 = __ldg(&erec[i]),     r1 = __ldg(&erec[i + 1]);
        int2 r2 = __ldg(&erec[i + 2]), r3 = __ldg(&erec[i + 3]);
        float4 v0 = __ldg(&h4[(size_t)((r0.x & 0x1FFFF) << 4) + lane]);
        float4 v1 = __ldg(&h4[(size_t)((r1.x & 0x1FFFF) << 4) + lane]);
        float4 v2 = __ldg(&h4[(size_t)((r2.x & 0x1FFFF) << 4) + lane]);
        float4 v3 = __ldg(&h4[(size_t)((r3.x & 0x1FFFF) << 4) + lane]);
        float w0 = __int_as_float(r0.y), w1 = __int_as_float(r1.y);
        float w2 = __int_as_float(r2.y), w3 = __int_as_float(r3.y);
        a0.x += w0*v0.x; a0.y += w0*v0.y; a0.z += w0*v0.z; a0.w += w0*v0.w;
        a1.x += w1*v1.x; a1.y += w1*v1.y; a1.z += w1*v1.z; a1.w += w1*v1.w;
        a2.x += w2*v2.x; a2.y += w2*v2.y; a2.z += w2*v2.z; a2.w += w2*v2.w;
        a3.x += w3*v3.x; a3.y += w3*v3.y; a3.z += w3*v3.z; a3.w += w3*v3.w;
    }
    for (; i < end; i++) {
        int2 r0 = __ldg(&erec[i]);
        float w0 = __int_as_float(r0.y);
        float4 v0 = __ldg(&h4[(size_t)((r0.x & 0x1FFFF) << 4) + lane]);
        a0.x += w0*v0.x; a0.y += w0*v0.y; a0.z += w0*v0.z; a0.w += w0*v0.w;
    }
    float4 o;
    o.x = (a0.x + a1.x) + (a2.x + a3.x);
    o.y = (a0.y + a1.y) + (a2.y + a3.y);
    o.z = (a0.z + a1.z) + (a2.z + a3.z);
    o.w = (a0.w + a1.w) + (a2.w + a3.w);
    *(float4*)&agg[((size_t)node << 6) + (lane << 2)] = o;
}

// ---------------- Group combine: h += alpha * ((agg*rdeg) @ W + b) ----------------
extern "C" __global__ void __launch_bounds__(256)
k_group_combine(const float* __restrict__ agg, const float* __restrict__ rdeg,
                const float* __restrict__ W, const float* __restrict__ b,
                const float* __restrict__ alpha_p, float* __restrict__ h, int N) {
    extern __shared__ float sm[];
    float* xs = sm;              // [64][XS_P]
    float* ws = sm + 64 * XS_P;  // [64][64]
    int t = threadIdx.x;
    int r0 = blockIdx.x * 128;

    for (int i = t; i < 128 * 64; i += 256) {
        int row = i >> 6, k = i & 63;
        int g = r0 + row;
        xs[k * XS_P + row] = (g < N) ? agg[(size_t)g * 64 + k] * rdeg[g] : 0.f;
    }
    for (int i = t; i < 64 * 64; i += 256) ws[i] = W[i];
    __syncthreads();

    float alpha = *alpha_p;
    int tx = t & 7, ty = t >> 3;
    const float* xp = &xs[4 * ty];

    unsigned long long acc[4][4];
    #pragma unroll
    for (int r = 0; r < 4; r++)
        #pragma unroll
        for (int j = 0; j < 4; j++) acc[r][j] = 0ULL;

    #pragma unroll 4
    for (int k = 0; k < 64; k++) {
        float4 xv = *(const float4*)&xp[k * XS_P];
        ulonglong2 wA = *(const ulonglong2*)&ws[k * 64 + 8 * tx];
        ulonglong2 wB = *(const ulonglong2*)&ws[k * 64 + 8 * tx + 4];
        unsigned long long x0 = pack2(xv.x), x1 = pack2(xv.y),
                           x2 = pack2(xv.z), x3 = pack2(xv.w);
        fma2(acc[0][0], x0, wA.x); fma2(acc[0][1], x0, wA.y);
        fma2(acc[0][2], x0, wB.x); fma2(acc[0][3], x0, wB.y);
        fma2(acc[1][0], x1, wA.x); fma2(acc[1][1], x1, wA.y);
        fma2(acc[1][2], x1, wB.x); fma2(acc[1][3], x1, wB.y);
        fma2(acc[2][0], x2, wA.x); fma2(acc[2][1], x2, wA.y);
        fma2(acc[2][2], x2, wB.x); fma2(acc[2][3], x2, wB.y);
        fma2(acc[3][0], x3, wA.x); fma2(acc[3][1], x3, wA.y);
        fma2(acc[3][2], x3, wB.x); fma2(acc[3][3], x3, wB.y);
    }
    float4 b0 = *(const float4*)&b[8 * tx];
    float4 b1 = *(const float4*)&b[8 * tx + 4];
    #pragma unroll
    for (int r = 0; r < 4; r++) {
        int gr = r0 + 4 * ty + r;
        if (gr < N) {
            float* hp = &h[((size_t)gr << 6) + 8 * tx];
            float4 h0 = *(float4*)hp;
            float4 h1 = *(float4*)(hp + 4);
            float2 f0 = unpack2(acc[r][0]), f1 = unpack2(acc[r][1]);
            float2 f2 = unpack2(acc[r][2]), f3 = unpack2(acc[r][3]);
            h0.x += alpha * (f0.x + b0.x); h0.y += alpha * (f0.y + b0.y);
            h0.z += alpha * (f1.x + b0.z); h0.w += alpha * (f1.y + b0.w);
            h1.x += alpha * (f2.x + b1.x); h1.y += alpha * (f2.y + b1.y);
            h1.z += alpha * (f3.x + b1.z); h1.w += alpha * (f3.y + b1.w);
            *(float4*)hp = h0;
            *(float4*)(hp + 4) = h1;
        }
    }
}

// ---------------- Output head: out = h @ outW[64,32] + outb ----------------
extern "C" __global__ void __launch_bounds__(256, 4)
k_head(const float* __restrict__ h, const float* __restrict__ W, const float* __restrict__ b,
       float* __restrict__ out, int N) {
    extern __shared__ float sm[];
    float* xs = sm;              // 128*65
    float* ws = sm + 128 * 65;   // 64*32
    int t = threadIdx.x;
    int r0 = blockIdx.x * 128;
    for (int i = t; i < 128 * 64; i += 256) {
        int rr = i >> 6, k = i & 63;
        int g = r0 + rr;
        xs[rr * 65 + k] = (g < N) ? h[(size_t)g * 64 + k] : 0.f;
    }
    for (int i = t; i < 64 * 32; i += 256) ws[i] = W[i];
    __syncthreads();
    int row = t & 127, th = t >> 7;
    int gr = r0 + row;
    const float* xrow = &xs[row * 65];
    for (int jt = 0; jt < 2; jt++) {
        int jl = (jt * 2 + th) * 8;
        unsigned long long a0 = 0, a1 = 0, a2 = 0, a3 = 0;
        #pragma unroll
        for (int k = 0; k < 64; k++) {
            unsigned long long xv = pack2(xrow[k]);
            const float* wp = &ws[k * 32 + jl];
            ulonglong2 wA = *(const ulonglong2*)wp;
            ulonglong2 wB = *(const ulonglong2*)(wp + 4);
            fma2(a0, xv, wA.x); fma2(a1, xv, wA.y);
            fma2(a2, xv, wB.x); fma2(a3, xv, wB.y);
        }
        if (gr < N) {
            float2 f0 = unpack2(a0), f1 = unpack2(a1), f2 = unpack2(a2), f3 = unpack2(a3);
            const float* bp = &b[jl];
            float* op = &out[(size_t)gr * 32 + jl];
            op[0] = f0.x + bp[0]; op[1] = f0.y + bp[1];
            op[2] = f1.x + bp[2]; op[3] = f1.y + bp[3];
            op[4] = f2.x + bp[4]; op[5] = f2.y + bp[5];
            op[6] = f3.x + bp[6]; op[7] = f3.y + bp[7];
        }
    }
}

// ---------------- launch ----------------
extern "C" void kernel_launch(void* const* d_in, const int* in_sizes, int n_in,
                              void* d_out, int out_size) {
    const float* x      = (const float*)d_in[0];
    const int*   ei     = (const int*)d_in[1];
    const int*   et     = (const int*)d_in[2];
    const float* ew     = (const float*)d_in[3];
    const float* W1     = (const float*)d_in[4];
    const float* W01    = (const float*)d_in[5];
    const float* alpha1 = (const float*)d_in[6];
    const float* projW1 = (const float*)d_in[7];
    const float* projb1 = (const float*)d_in[8];
    const float* W2     = (const float*)d_in[9];
    const float* W02    = (const float*)d_in[10];
    const float* alpha2 = (const float*)d_in[11];
    const float* projW2 = (const float*)d_in[12];
    const float* projb2 = (const float*)d_in[13];
    const float* outW   = (const float*)d_in[14];
    const float* outb   = (const float*)d_in[15];

    int N = in_sizes[0] / 64;
    int E = in_sizes[2];

    float *rdeg, *xt, *agg, *h;
    int *cnt, *off, *cursor, *bsum;
    int2 *erec;
    cudaGetSymbolAddress((void**)&rdeg,   g_rdeg);
    cudaGetSymbolAddress((void**)&cnt,    g_cnt);
    cudaGetSymbolAddress((void**)&off,    g_off);
    cudaGetSymbolAddress((void**)&cursor, g_cursor);
    cudaGetSymbolAddress((void**)&bsum,   g_bsum);
    cudaGetSymbolAddress((void**)&erec,   g_erec);
    cudaGetSymbolAddress((void**)&xt,     g_xt);
    cudaGetSymbolAddress((void**)&agg,    g_agg);
    cudaGetSymbolAddress((void**)&h,      g_h);

    // side stream + events for CSR/transform overlap (created once; host objects only)
    static cudaStream_t s2 = nullptr;
    static cudaEvent_t evFork = nullptr, evJoin = nullptr;
    if (s2 == nullptr) {
        cudaStreamCreateWithFlags(&s2, cudaStreamNonBlocking);
        cudaEventCreateWithFlags(&evFork, cudaEventDisableTiming);
        cudaEventCreateWithFlags(&evJoin, cudaEventDisableTiming);
    }

    const int SMEM_T = (64 * XS_P + 64 * 64) * 4;
    const int SMEM_H = (128 * 65 + 64 * 32) * 4;
    cudaFuncSetAttribute(k_transform,     cudaFuncAttributeMaxDynamicSharedMemorySize, SMEM_T);
    cudaFuncSetAttribute(k_group_combine, cudaFuncAttributeMaxDynamicSharedMemorySize, SMEM_T);
    cudaFuncSetAttribute(k_head,          cudaFuncAttributeMaxDynamicSharedMemorySize, SMEM_H);

    int ebl  = (E + 255) / 256;
    int nbl  = (N + 255) / 256;
    int gthr = (N * 16 + 255) / 256;
    int gbl  = (N + 127) / 128;
    int B1   = (N + 1023) / 1024;

    // ---- fork: CSR build on s2, transform layer 1 on main stream ----
    cudaEventRecord(evFork, 0);
    cudaStreamWaitEvent(s2, evFork, 0);

    cudaMemsetAsync(cnt, 0, (size_t)N * sizeof(int), s2);
    k_deg<<<ebl, 256, 0, s2>>>(ei, cnt, E);
    k_scan1<<<B1, 1024, 0, s2>>>(cnt, off, rdeg, bsum, N);
    k_scan2<<<1, 64, 0, s2>>>(bsum, B1);
    k_scan3<<<nbl, 256, 0, s2>>>(off, cursor, bsum, N, E);
    k_fill<<<ebl, 256, 0, s2>>>(ei, et, ew, cursor, erec, E);
    cudaEventRecord(evJoin, s2);

    k_transform<<<gbl, 256, SMEM_T>>>(x, W01, W1, xt, N);

    cudaStreamWaitEvent(0, evJoin, 0);   // join before first gather

    // ---- layer 1 ----
    k_rgcn_gather<<<gthr, 256>>>(off, erec, xt, rdeg, h, N);
    k_group_gather<<<gthr, 256>>>(off, erec, h, agg, N);
    k_group_combine<<<gbl, 256, SMEM_T>>>(agg, rdeg, projW1, projb1, alpha1, h, N);

    // ---- layer 2 ----
    k_transform<<<gbl, 256, SMEM_T>>>(h, W02, W2, xt, N);
    k_rgcn_gather<<<gthr, 256>>>(off, erec, xt, rdeg, h, N);
    k_group_gather<<<gthr, 256>>>(off, erec, h, agg, N);
    k_group_combine<<<gbl, 256, SMEM_T>>>(agg, rdeg, projW2, projb2, alpha2, h, N);

    // ---- head ----
    k_head<<<gbl, 256, SMEM_H>>>(h, outW, outb, (float*)d_out, N);
}